// round 4
// baseline (speedup 1.0000x reference)
#include <cuda_runtime.h>
#include <math.h>

#define N_NODES_MAX 100000
#define N_EDGES_MAX 1600000
#define DIM 128
#define NCLS 40

// ---------------- scratch (static device allocations; no cudaMalloc) -------
__device__ int g_deg[N_NODES_MAX];
__device__ int g_offs[N_NODES_MAX + 1];
__device__ int g_cur[N_NODES_MAX];
__device__ int g_csr[N_EDGES_MAX];
__device__ __align__(16) float g_agg[(size_t)N_NODES_MAX * DIM];
__device__ __align__(16) float g_x1[(size_t)N_NODES_MAX * DIM];

// ---------------- CSR build -------------------------------------------------
__global__ void zero_deg_kernel(int n) {
    int i = blockIdx.x * blockDim.x + threadIdx.x;
    if (i < n) g_deg[i] = 0;
}

__global__ void hist_kernel(const int2* __restrict__ e, int m) {
    int i = blockIdx.x * blockDim.x + threadIdx.x;
    if (i < m) atomicAdd(&g_deg[e[i].y], 1);
}

// Single-block chunked exclusive scan: deg -> offs, cursor copy.
__global__ void scan_kernel(int n) {
    int t = threadIdx.x;
    int chunk = (n + 1023) >> 10;
    int b = t * chunk;
    int e = b + chunk;
    if (e > n) e = n;
    if (b > n) b = n;
    int sum = 0;
    for (int i = b; i < e; i++) sum += g_deg[i];

    int lane = t & 31, wid = t >> 5;
    int v = sum;
#pragma unroll
    for (int o = 1; o < 32; o <<= 1) {
        int u = __shfl_up_sync(0xffffffffu, v, o);
        if (lane >= o) v += u;
    }
    __shared__ int ws[32];
    if (lane == 31) ws[wid] = v;
    __syncthreads();
    if (wid == 0) {
        int w = ws[lane];
#pragma unroll
        for (int o = 1; o < 32; o <<= 1) {
            int u = __shfl_up_sync(0xffffffffu, w, o);
            if (lane >= o) w += u;
        }
        ws[lane] = w;
    }
    __syncthreads();
    int base = ((wid > 0) ? ws[wid - 1] : 0) + (v - sum);
    int run = base;
    for (int i = b; i < e; i++) {
        g_offs[i] = run;
        g_cur[i] = run;
        run += g_deg[i];
    }
    if (e == n) g_offs[n] = run;  // every writer holds the grand total here
}

__global__ void fill_kernel(const int2* __restrict__ e, int m) {
    int i = blockIdx.x * blockDim.x + threadIdx.x;
    if (i < m) {
        int2 ed = e[i];
        int p = atomicAdd(&g_cur[ed.y], 1);
        g_csr[p] = ed.x;
    }
}

// ---------------- aggregation: warp per node, gather-only -------------------
// out = x + sum_{s in N(i)} x[s]   (GIN eps=0: agg + x)
__global__ __launch_bounds__(256) void agg_kernel(const float4* __restrict__ xin,
                                                  int n, int from_x1) {
    int gt = blockIdx.x * blockDim.x + threadIdx.x;
    int w = gt >> 5;
    int lane = gt & 31;
    if (w >= n) return;
    const float4* x4 = from_x1 ? (const float4*)g_x1 : xin;
    float4* o4 = (float4*)g_agg;
    float4 acc = x4[(size_t)w * 32 + lane];
    int s0 = g_offs[w], s1 = g_offs[w + 1];
    for (int j = s0; j < s1; j++) {
        int s = g_csr[j];
        float4 v = __ldg(&x4[(size_t)s * 32 + lane]);
        acc.x += v.x; acc.y += v.y; acc.z += v.z; acc.w += v.w;
    }
    o4[(size_t)w * 32 + lane] = acc;
}

// ---------------- layer 1: x1 = relu(relu(agg@W1a+b1a)@W1b + b1b) -----------
#define G1_SMEM_FLOATS (64 * 129 + 128 * 128 + 128 + 128)
__global__ __launch_bounds__(256) void gemm1_kernel(
    const float* __restrict__ W1a, const float* __restrict__ b1a,
    const float* __restrict__ W1b, const float* __restrict__ b1b, int n) {
    extern __shared__ float sm[];
    float* As = sm;                    // 64 x 129 (padded)
    float* Wsh = sm + 64 * 129;        // 128 x 128
    float* bsA = Wsh + 128 * 128;      // 128
    float* bsB = bsA + 128;            // 128

    int tid = threadIdx.x;
    int tx = tid & 15, ty = tid >> 4;  // 16x16 thread grid; thread owns 4x8 tile
    int row0 = blockIdx.x * 64;
    const float* A = g_agg;
    float* out = g_x1;

    // stage A tile (zero-fill OOB rows)
    for (int i = tid; i < 64 * 32; i += 256) {
        int r = i >> 5, c = i & 31;
        float4 v = (row0 + r < n) ? ((const float4*)A)[(size_t)(row0 + r) * 32 + c]
                                  : make_float4(0.f, 0.f, 0.f, 0.f);
        float* d = &As[r * 129 + c * 4];
        d[0] = v.x; d[1] = v.y; d[2] = v.z; d[3] = v.w;
    }
    for (int i = tid; i < 128 * 32; i += 256)
        ((float4*)Wsh)[i] = ((const float4*)W1a)[i];
    if (tid < 128) { bsA[tid] = b1a[tid]; bsB[tid] = b1b[tid]; }
    __syncthreads();

    float acc[4][8];
#pragma unroll
    for (int r = 0; r < 4; r++)
#pragma unroll
        for (int c = 0; c < 8; c++) acc[r][c] = 0.f;

    const float* a0 = &As[(ty * 4) * 129];
#pragma unroll 8
    for (int k = 0; k < 128; k++) {
        float av[4];
#pragma unroll
        for (int r = 0; r < 4; r++) av[r] = a0[r * 129 + k];
        float4 w0 = *(const float4*)&Wsh[k * 128 + tx * 8];
        float4 w1 = *(const float4*)&Wsh[k * 128 + tx * 8 + 4];
#pragma unroll
        for (int r = 0; r < 4; r++) {
            acc[r][0] = fmaf(av[r], w0.x, acc[r][0]);
            acc[r][1] = fmaf(av[r], w0.y, acc[r][1]);
            acc[r][2] = fmaf(av[r], w0.z, acc[r][2]);
            acc[r][3] = fmaf(av[r], w0.w, acc[r][3]);
            acc[r][4] = fmaf(av[r], w1.x, acc[r][4]);
            acc[r][5] = fmaf(av[r], w1.y, acc[r][5]);
            acc[r][6] = fmaf(av[r], w1.z, acc[r][6]);
            acc[r][7] = fmaf(av[r], w1.w, acc[r][7]);
        }
    }
    __syncthreads();  // everyone finished reading As + Wsh

    // H = relu(acc + b1a) back into As; swap W1b into Wsh
#pragma unroll
    for (int r = 0; r < 4; r++)
#pragma unroll
        for (int c = 0; c < 8; c++) {
            As[(ty * 4 + r) * 129 + tx * 8 + c] = fmaxf(acc[r][c] + bsA[tx * 8 + c], 0.f);
            acc[r][c] = 0.f;
        }
    for (int i = tid; i < 128 * 32; i += 256)
        ((float4*)Wsh)[i] = ((const float4*)W1b)[i];
    __syncthreads();

#pragma unroll 8
    for (int k = 0; k < 128; k++) {
        float av[4];
#pragma unroll
        for (int r = 0; r < 4; r++) av[r] = a0[r * 129 + k];
        float4 w0 = *(const float4*)&Wsh[k * 128 + tx * 8];
        float4 w1 = *(const float4*)&Wsh[k * 128 + tx * 8 + 4];
#pragma unroll
        for (int r = 0; r < 4; r++) {
            acc[r][0] = fmaf(av[r], w0.x, acc[r][0]);
            acc[r][1] = fmaf(av[r], w0.y, acc[r][1]);
            acc[r][2] = fmaf(av[r], w0.z, acc[r][2]);
            acc[r][3] = fmaf(av[r], w0.w, acc[r][3]);
            acc[r][4] = fmaf(av[r], w1.x, acc[r][4]);
            acc[r][5] = fmaf(av[r], w1.y, acc[r][5]);
            acc[r][6] = fmaf(av[r], w1.z, acc[r][6]);
            acc[r][7] = fmaf(av[r], w1.w, acc[r][7]);
        }
    }

    // x1 = relu(acc + b1b), store coalesced float4
#pragma unroll
    for (int r = 0; r < 4; r++) {
        int row = row0 + ty * 4 + r;
        if (row < n) {
            float4 o0, o1;
            o0.x = fmaxf(acc[r][0] + bsB[tx * 8 + 0], 0.f);
            o0.y = fmaxf(acc[r][1] + bsB[tx * 8 + 1], 0.f);
            o0.z = fmaxf(acc[r][2] + bsB[tx * 8 + 2], 0.f);
            o0.w = fmaxf(acc[r][3] + bsB[tx * 8 + 3], 0.f);
            o1.x = fmaxf(acc[r][4] + bsB[tx * 8 + 4], 0.f);
            o1.y = fmaxf(acc[r][5] + bsB[tx * 8 + 5], 0.f);
            o1.z = fmaxf(acc[r][6] + bsB[tx * 8 + 6], 0.f);
            o1.w = fmaxf(acc[r][7] + bsB[tx * 8 + 7], 0.f);
            float4* dst = (float4*)&out[(size_t)row * 128 + tx * 8];
            dst[0] = o0;
            dst[1] = o1;
        }
    }
}

// ---------------- layer 2 + softmax: out = softmax(relu(agg@W2a+b2a)@W2b+b2b)
#define G2_SMEM_FLOATS (128 * 129 + 128 * 40 + 40 * 40 + 40 + 40)
__global__ __launch_bounds__(128) void gemm2_kernel(
    const float* __restrict__ W2a, const float* __restrict__ b2a,
    const float* __restrict__ W2b, const float* __restrict__ b2b,
    float* __restrict__ out, int n) {
    extern __shared__ float sm[];
    float* As = sm;                  // 128 x 129 (padded)
    float* Wa = sm + 128 * 129;      // 128 x 40
    float* Wb = Wa + 128 * 40;       // 40 x 40
    float* ba = Wb + 40 * 40;        // 40
    float* bb = ba + 40;             // 40

    int tid = threadIdx.x;
    int row0 = blockIdx.x * 128;
    const float* A = g_agg;

    for (int i = tid; i < 128 * 32; i += 128) {
        int r = i >> 5, c = i & 31;
        float4 v = (row0 + r < n) ? ((const float4*)A)[(size_t)(row0 + r) * 32 + c]
                                  : make_float4(0.f, 0.f, 0.f, 0.f);
        float* d = &As[r * 129 + c * 4];
        d[0] = v.x; d[1] = v.y; d[2] = v.z; d[3] = v.w;
    }
    for (int i = tid; i < 128 * 10; i += 128)
        ((float4*)Wa)[i] = ((const float4*)W2a)[i];
    // FIX (was the bug all along): W2b has 40*40 = 1600 elements, not 400.
    for (int i = tid; i < 1600; i += 128) Wb[i] = W2b[i];
    if (tid < 40) { ba[tid] = b2a[tid]; bb[tid] = b2b[tid]; }
    __syncthreads();

    float h[40];
#pragma unroll
    for (int c = 0; c < 40; c++) h[c] = ba[c];
    const float* arow = &As[tid * 129];
    for (int k = 0; k < 128; k++) {
        float a = arow[k];
        const float4* w = (const float4*)&Wa[k * 40];
#pragma unroll
        for (int q = 0; q < 10; q++) {
            float4 wv = w[q];
            h[q * 4 + 0] = fmaf(a, wv.x, h[q * 4 + 0]);
            h[q * 4 + 1] = fmaf(a, wv.y, h[q * 4 + 1]);
            h[q * 4 + 2] = fmaf(a, wv.z, h[q * 4 + 2]);
            h[q * 4 + 3] = fmaf(a, wv.w, h[q * 4 + 3]);
        }
    }
    float o[40];
#pragma unroll
    for (int c = 0; c < 40; c++) { o[c] = bb[c]; h[c] = fmaxf(h[c], 0.f); }
#pragma unroll 4
    for (int k = 0; k < 40; k++) {
        float a = h[k];
        const float4* w = (const float4*)&Wb[k * 40];
#pragma unroll
        for (int q = 0; q < 10; q++) {
            float4 wv = w[q];
            o[q * 4 + 0] = fmaf(a, wv.x, o[q * 4 + 0]);
            o[q * 4 + 1] = fmaf(a, wv.y, o[q * 4 + 1]);
            o[q * 4 + 2] = fmaf(a, wv.z, o[q * 4 + 2]);
            o[q * 4 + 3] = fmaf(a, wv.w, o[q * 4 + 3]);
        }
    }
    // softmax over 40
    float mx = o[0];
#pragma unroll
    for (int c = 1; c < 40; c++) mx = fmaxf(mx, o[c]);
    float s = 0.f;
#pragma unroll
    for (int c = 0; c < 40; c++) { float e = __expf(o[c] - mx); o[c] = e; s += e; }
    float inv = 1.0f / s;
#pragma unroll
    for (int c = 0; c < 40; c++) o[c] *= inv;

    // restage in smem (own row only) for coalesced global store
#pragma unroll
    for (int c = 0; c < 40; c++) As[tid * 129 + c] = o[c];
    __syncthreads();
    for (int i = tid; i < 128 * 40; i += 128) {
        int r = i / 40, c = i - r * 40;
        int row = row0 + r;
        if (row < n) out[(size_t)row * 40 + c] = As[r * 129 + c];
    }
}

// ---------------- launcher --------------------------------------------------
// Inputs identified BY ELEMENT COUNT (permutation-invariant):
//   node_embeddings : N*128 (largest)   edge_index : E*2 (2nd largest)
//   W1a,W1b : 16384 each (first occurrence = W1a)   b1a,b1b : 128 (zeros)
//   W2a : 5120   W2b : 1600   b2a,b2b : 40 (zeros)
extern "C" void kernel_launch(void* const* d_in, const int* in_sizes, int n_in,
                              void* d_out, int out_size) {
    int i_nodes = 0, i_edges = -1;
    for (int i = 1; i < n_in; i++)
        if (in_sizes[i] > in_sizes[i_nodes]) i_nodes = i;
    for (int i = 0; i < n_in; i++) {
        if (i == i_nodes) continue;
        if (i_edges < 0 || in_sizes[i] > in_sizes[i_edges]) i_edges = i;
    }

    const float* x0  = (const float*)d_in[i_nodes];
    const int2*  ei  = (const int2*)d_in[i_edges];
    int n = in_sizes[i_nodes] / DIM;
    int m = in_sizes[i_edges] / 2;

    const float *W1a = 0, *W1b = 0, *b1a = 0, *b1b = 0;
    const float *W2a = 0, *W2b = 0, *b2a = 0, *b2b = 0;
    for (int i = 0; i < n_in; i++) {
        if (i == i_nodes || i == i_edges) continue;
        int s = in_sizes[i];
        const float* p = (const float*)d_in[i];
        if (s == DIM * DIM)        { if (!W1a) W1a = p; else W1b = p; }
        else if (s == DIM)         { if (!b1a) b1a = p; else b1b = p; }
        else if (s == DIM * NCLS)  W2a = p;
        else if (s == NCLS * NCLS) W2b = p;
        else if (s == NCLS)        { if (!b2a) b2a = p; else b2b = p; }
    }
    float* out = (float*)d_out;

    const int g1_smem = G1_SMEM_FLOATS * (int)sizeof(float);
    const int g2_smem = G2_SMEM_FLOATS * (int)sizeof(float);
    cudaFuncSetAttribute(gemm1_kernel, cudaFuncAttributeMaxDynamicSharedMemorySize, g1_smem);
    cudaFuncSetAttribute(gemm2_kernel, cudaFuncAttributeMaxDynamicSharedMemorySize, g2_smem);

    // CSR build (shared by both layers)
    zero_deg_kernel<<<(n + 255) / 256, 256>>>(n);
    hist_kernel<<<(m + 255) / 256, 256>>>(ei, m);
    scan_kernel<<<1, 1024>>>(n);
    fill_kernel<<<(m + 255) / 256, 256>>>(ei, m);

    // layer 1
    agg_kernel<<<((size_t)n * 32 + 255) / 256, 256>>>((const float4*)x0, n, 0);
    gemm1_kernel<<<(n + 63) / 64, 256, g1_smem>>>(W1a, b1a, W1b, b1b, n);

    // layer 2
    agg_kernel<<<((size_t)n * 32 + 255) / 256, 256>>>((const float4*)x0, n, 1);
    gemm2_kernel<<<(n + 127) / 128, 128, g2_smem>>>(W2a, b2a, W2b, b2b, out, n);
}